// round 1
// baseline (speedup 1.0000x reference)
#include <cuda_runtime.h>
#include <math.h>

// Problem constants
#define T_SEQ 384
#define N_NEU 128
#define D_MOD 512
#define H_HEADS 8
#define DHEAD 64
#define M_ROWS (N_NEU * T_SEQ)   // 49152
#define QKV_ELEMS (N_NEU * H_HEADS * T_SEQ * DHEAD)  // 25165824

// Scratch (device globals; allocation inside kernel_launch is forbidden)
__device__ float g_XN[N_NEU * T_SEQ * D_MOD];   // rmsnormed x, (n, t, d) layout
__device__ float g_Q[QKV_ELEMS];                // (r*8+h, t, dh)
__device__ float g_K[QKV_ELEMS];
__device__ float g_V[QKV_ELEMS];
__device__ float g_Y[M_ROWS * D_MOD];           // (t*128+n, d): masked attn out + residual

// ---------------------------------------------------------------------------
// Kernel 1: RMSNorm + transpose (t,n,d) -> (n,t,d)
// one block (128 threads) per row; each thread handles one float4 (512 = 128*4)
// ---------------------------------------------------------------------------
__global__ void rmsnorm_kernel(const float* __restrict__ x,
                               const float* __restrict__ w,
                               float* __restrict__ xn) {
    int row = blockIdx.x;          // row = t*128 + n
    int t = row >> 7;
    int n = row & 127;
    int tid = threadIdx.x;

    float4 v = ((const float4*)(x + (size_t)row * D_MOD))[tid];
    float ss = v.x * v.x + v.y * v.y + v.z * v.z + v.w * v.w;
    #pragma unroll
    for (int m = 16; m; m >>= 1) ss += __shfl_xor_sync(0xffffffffu, ss, m);

    __shared__ float sbuf[4];
    if ((tid & 31) == 0) sbuf[tid >> 5] = ss;
    __syncthreads();
    float tot = sbuf[0] + sbuf[1] + sbuf[2] + sbuf[3];
    float inv = rsqrtf(tot * (1.0f / (float)D_MOD) + 1e-6f);

    float4 wv = ((const float4*)w)[tid];
    float4 o;
    o.x = v.x * inv * wv.x;
    o.y = v.y * inv * wv.y;
    o.z = v.z * inv * wv.z;
    o.w = v.w * inv * wv.w;
    ((float4*)(g_XN + ((size_t)n * T_SEQ + t) * D_MOD))[tid] = o;
    (void)xn;
}

// ---------------------------------------------------------------------------
// Kernel 2: QKV projection.  C[m][c] = sum_d XN[m][d] * W[c][d]
// M = 49152, N = 1536 (cols 0..511 -> Q with wq, 512..1023 -> K, 1024.. -> V)
// 64x64 block tile, BK=16, 256 threads, 4x4 per thread.
// Output written directly in (r*8+h, t, dh) layout.
// ---------------------------------------------------------------------------
__global__ void qkv_gemm_kernel(const float* __restrict__ wq,
                                const float* __restrict__ wk,
                                const float* __restrict__ wv) {
    __shared__ float As[16][65];
    __shared__ float Bs[16][65];

    int n0 = blockIdx.x * 64;            // 0..1535
    int m0 = blockIdx.y * 64;
    int which = n0 >> 9;                 // 0,1,2
    int cc0 = n0 & 511;                  // weight row base
    const float* W = (which == 0) ? wq : ((which == 1) ? wk : wv);
    float* Dst = (which == 0) ? g_Q : ((which == 1) ? g_K : g_V);
    int h = cc0 >> 6;                    // constant per block

    int tid = threadIdx.x;
    int lrow = tid >> 2;                 // 0..63
    int kseg = (tid & 3) << 2;           // 0,4,8,12
    int ty = tid >> 4, tx = tid & 15;
    int row0 = ty * 4, col0 = tx * 4;

    float acc[4][4] = {};

    const float* A = g_XN;
    for (int kb = 0; kb < 512; kb += 16) {
        float4 a4 = *(const float4*)(A + (size_t)(m0 + lrow) * 512 + kb + kseg);
        float4 b4 = *(const float4*)(W + (size_t)(cc0 + lrow) * 512 + kb + kseg);
        As[kseg + 0][lrow] = a4.x; As[kseg + 1][lrow] = a4.y;
        As[kseg + 2][lrow] = a4.z; As[kseg + 3][lrow] = a4.w;
        Bs[kseg + 0][lrow] = b4.x; Bs[kseg + 1][lrow] = b4.y;
        Bs[kseg + 2][lrow] = b4.z; Bs[kseg + 3][lrow] = b4.w;
        __syncthreads();
        #pragma unroll
        for (int kk = 0; kk < 16; kk++) {
            float a[4], b[4];
            #pragma unroll
            for (int i = 0; i < 4; i++) a[i] = As[kk][row0 + i];
            #pragma unroll
            for (int j = 0; j < 4; j++) b[j] = Bs[kk][col0 + j];
            #pragma unroll
            for (int i = 0; i < 4; i++)
                #pragma unroll
                for (int j = 0; j < 4; j++) acc[i][j] += a[i] * b[j];
        }
        __syncthreads();
    }

    #pragma unroll
    for (int i = 0; i < 4; i++) {
        int m = m0 + row0 + i;
        int r = m / T_SEQ, t = m % T_SEQ;
        float4 val = make_float4(acc[i][0], acc[i][1], acc[i][2], acc[i][3]);
        *(float4*)(Dst + (((size_t)(r * H_HEADS + h) * T_SEQ) + t) * DHEAD + col0) = val;
    }
}

// ---------------------------------------------------------------------------
// Kernel 3: RoPE on Q and K (rotary dim 32, interleaved pairs),
// plus pre-scale of the full Q row by 1/sqrt(Dh) = 0.125.
// one warp per (rh, t) row.
// ---------------------------------------------------------------------------
__global__ void rope_kernel() {
    int warp = (blockIdx.x << 2) + (threadIdx.x >> 5);  // 0 .. 1024*384-1
    int lane = threadIdx.x & 31;
    int rh = warp / T_SEQ;
    int t = warp - rh * T_SEQ;
    size_t base = ((size_t)rh * T_SEQ + t) * DHEAD;

    if (lane < 16) {
        int i = lane;
        // inv_freq = 10000^(-2i/32) = exp(-i * ln(10000)/16)
        float invf = __expf(-(float)i * (9.210340371976184f / 16.0f));
        float ang = (float)t * invf;
        float s = sinf(ang), c = cosf(ang);

        float qa = g_Q[base + 2 * i], qb = g_Q[base + 2 * i + 1];
        g_Q[base + 2 * i]     = (qa * c - qb * s) * 0.125f;
        g_Q[base + 2 * i + 1] = (qa * s + qb * c) * 0.125f;

        float ka = g_K[base + 2 * i], kb = g_K[base + 2 * i + 1];
        g_K[base + 2 * i]     = ka * c - kb * s;
        g_K[base + 2 * i + 1] = ka * s + kb * c;
    } else {
        int j = lane - 16;
        int d = 32 + 2 * j;
        g_Q[base + d]     *= 0.125f;
        g_Q[base + d + 1] *= 0.125f;
    }
}

// ---------------------------------------------------------------------------
// Kernel 4: causal flash attention, one block per (q-tile of 64, rh pair).
// Fused epilogue: pad-mask + residual add + transpose into (t, n, d) layout.
// 256 threads = 16x16; S phase: thread owns 4 qrows x 4 kcols;
// PV phase: 4 qrows x 4 dh cols.
// Dynamic smem: Qs, Ks, Vs, Ps each [64][65] floats = 66560 B.
// ---------------------------------------------------------------------------
__global__ void attn_kernel(const int* __restrict__ pad_mask) {
    extern __shared__ float sm[];
    float (*Qs)[65] = (float (*)[65])(sm);
    float (*Ks)[65] = (float (*)[65])(sm + 64 * 65);
    float (*Vs)[65] = (float (*)[65])(sm + 2 * 64 * 65);
    float (*Ps)[65] = (float (*)[65])(sm + 3 * 64 * 65);

    int qt = blockIdx.x;
    int rh = blockIdx.y;
    int r = rh >> 3, h = rh & 7;
    int qbase = qt * 64;

    int tid = threadIdx.x;
    int ty = tid >> 4, tx = tid & 15;
    int qr0 = ty * 4;
    int kc0 = tx * 4;   // key cols in S phase
    int dh0 = tx * 4;   // dh cols in PV phase

    // load Q tile
    const float* Qp = g_Q + ((size_t)rh * T_SEQ + qbase) * DHEAD;
    for (int f = tid; f < 64 * 16; f += 256) {
        int row = f >> 4, c4 = (f & 15) << 2;
        float4 v = *(const float4*)(Qp + row * DHEAD + c4);
        Qs[row][c4] = v.x; Qs[row][c4 + 1] = v.y;
        Qs[row][c4 + 2] = v.z; Qs[row][c4 + 3] = v.w;
    }

    float o[4][4] = {};
    float mrow[4] = {-1e30f, -1e30f, -1e30f, -1e30f};
    float lrow[4] = {0.f, 0.f, 0.f, 0.f};

    int ntiles = qt + 1;
    for (int kt = 0; kt < ntiles; kt++) {
        int kbase = kt * 64;
        __syncthreads();   // previous iteration done reading smem (also covers Q load)
        const float* Kp = g_K + ((size_t)rh * T_SEQ + kbase) * DHEAD;
        const float* Vp = g_V + ((size_t)rh * T_SEQ + kbase) * DHEAD;
        for (int f = tid; f < 64 * 16; f += 256) {
            int row = f >> 4, c4 = (f & 15) << 2;
            float4 kv = *(const float4*)(Kp + row * DHEAD + c4);
            Ks[row][c4] = kv.x; Ks[row][c4 + 1] = kv.y;
            Ks[row][c4 + 2] = kv.z; Ks[row][c4 + 3] = kv.w;
            float4 vv = *(const float4*)(Vp + row * DHEAD + c4);
            Vs[row][c4] = vv.x; Vs[row][c4 + 1] = vv.y;
            Vs[row][c4 + 2] = vv.z; Vs[row][c4 + 3] = vv.w;
        }
        __syncthreads();

        // S = Q K^T (q pre-scaled by 0.125)
        float s[4][4] = {};
        #pragma unroll
        for (int d = 0; d < 64; d++) {
            float qa[4], kb[4];
            #pragma unroll
            for (int i = 0; i < 4; i++) qa[i] = Qs[qr0 + i][d];
            #pragma unroll
            for (int j = 0; j < 4; j++) kb[j] = Ks[kc0 + j][d];
            #pragma unroll
            for (int i = 0; i < 4; i++)
                #pragma unroll
                for (int j = 0; j < 4; j++) s[i][j] += qa[i] * kb[j];
        }

        // causal mask + online softmax update
        #pragma unroll
        for (int i = 0; i < 4; i++) {
            int tq = qbase + qr0 + i;
            float tmax = -1e30f;
            #pragma unroll
            for (int j = 0; j < 4; j++) {
                bool ok = (kbase + kc0 + j) <= tq;
                s[i][j] = ok ? s[i][j] : -1e30f;
                tmax = fmaxf(tmax, s[i][j]);
            }
            #pragma unroll
            for (int msk = 1; msk < 16; msk <<= 1)
                tmax = fmaxf(tmax, __shfl_xor_sync(0xffffffffu, tmax, msk));
            float nm = fmaxf(mrow[i], tmax);
            float scl = __expf(mrow[i] - nm);
            float ts = 0.f;
            #pragma unroll
            for (int j = 0; j < 4; j++) {
                float p = __expf(s[i][j] - nm);
                s[i][j] = p;
                ts += p;
            }
            #pragma unroll
            for (int msk = 1; msk < 16; msk <<= 1)
                ts += __shfl_xor_sync(0xffffffffu, ts, msk);
            lrow[i] = lrow[i] * scl + ts;
            mrow[i] = nm;
            #pragma unroll
            for (int j = 0; j < 4; j++) o[i][j] *= scl;
        }

        // write P
        #pragma unroll
        for (int i = 0; i < 4; i++)
            #pragma unroll
            for (int j = 0; j < 4; j++) Ps[qr0 + i][kc0 + j] = s[i][j];
        __syncthreads();

        // O += P @ V
        #pragma unroll
        for (int kc = 0; kc < 64; kc++) {
            float pa[4], vb[4];
            #pragma unroll
            for (int i = 0; i < 4; i++) pa[i] = Ps[qr0 + i][kc];
            #pragma unroll
            for (int j = 0; j < 4; j++) vb[j] = Vs[kc][dh0 + j];
            #pragma unroll
            for (int i = 0; i < 4; i++)
                #pragma unroll
                for (int j = 0; j < 4; j++) o[i][j] += pa[i] * vb[j];
        }
    }

    // epilogue: mask, residual, transpose to (t, n, d)
    bool valid = (pad_mask[r] != 0);
    #pragma unroll
    for (int i = 0; i < 4; i++) {
        int tq = qbase + qr0 + i;
        float invl = 1.0f / lrow[i];
        const float* xr = g_XN + ((size_t)r * T_SEQ + tq) * D_MOD + h * DHEAD + dh0;
        float* yp = g_Y + ((size_t)tq * N_NEU + r) * D_MOD + h * DHEAD + dh0;
        float4 res = *(const float4*)xr;
        float4 ov;
        ov.x = (valid ? o[i][0] * invl : 0.f) + res.x;
        ov.y = (valid ? o[i][1] * invl : 0.f) + res.y;
        ov.z = (valid ? o[i][2] * invl : 0.f) + res.z;
        ov.w = (valid ? o[i][3] * invl : 0.f) + res.w;
        *(float4*)yp = ov;
    }
}

// ---------------------------------------------------------------------------
// Kernel 5: output projection. out[m][c] = sum_d Y[m][d] * wo[c][d]
// M = 49152, N = 512. Same tiling as qkv_gemm.
// ---------------------------------------------------------------------------
__global__ void out_gemm_kernel(const float* __restrict__ wo,
                                float* __restrict__ out) {
    __shared__ float As[16][65];
    __shared__ float Bs[16][65];

    int n0 = blockIdx.x * 64;
    int m0 = blockIdx.y * 64;
    int tid = threadIdx.x;
    int lrow = tid >> 2;
    int kseg = (tid & 3) << 2;
    int ty = tid >> 4, tx = tid & 15;
    int row0 = ty * 4, col0 = tx * 4;

    float acc[4][4] = {};

    for (int kb = 0; kb < 512; kb += 16) {
        float4 a4 = *(const float4*)(g_Y + (size_t)(m0 + lrow) * 512 + kb + kseg);
        float4 b4 = *(const float4*)(wo + (size_t)(n0 + lrow) * 512 + kb + kseg);
        As[kseg + 0][lrow] = a4.x; As[kseg + 1][lrow] = a4.y;
        As[kseg + 2][lrow] = a4.z; As[kseg + 3][lrow] = a4.w;
        Bs[kseg + 0][lrow] = b4.x; Bs[kseg + 1][lrow] = b4.y;
        Bs[kseg + 2][lrow] = b4.z; Bs[kseg + 3][lrow] = b4.w;
        __syncthreads();
        #pragma unroll
        for (int kk = 0; kk < 16; kk++) {
            float a[4], b[4];
            #pragma unroll
            for (int i = 0; i < 4; i++) a[i] = As[kk][row0 + i];
            #pragma unroll
            for (int j = 0; j < 4; j++) b[j] = Bs[kk][col0 + j];
            #pragma unroll
            for (int i = 0; i < 4; i++)
                #pragma unroll
                for (int j = 0; j < 4; j++) acc[i][j] += a[i] * b[j];
        }
        __syncthreads();
    }

    #pragma unroll
    for (int i = 0; i < 4; i++) {
        int m = m0 + row0 + i;
        float4 val = make_float4(acc[i][0], acc[i][1], acc[i][2], acc[i][3]);
        *(float4*)(out + (size_t)m * 512 + n0 + col0) = val;
    }
}

// ---------------------------------------------------------------------------
extern "C" void kernel_launch(void* const* d_in, const int* in_sizes, int n_in,
                              void* d_out, int out_size) {
    const float* x       = (const float*)d_in[0];
    const int*   pad     = (const int*)d_in[1];
    const float* norm_w  = (const float*)d_in[2];
    const float* wq      = (const float*)d_in[3];
    const float* wk      = (const float*)d_in[4];
    const float* wv      = (const float*)d_in[5];
    const float* wo      = (const float*)d_in[6];
    float* out = (float*)d_out;
    (void)in_sizes; (void)n_in; (void)out_size;

    // attention kernel needs >48KB dynamic smem
    cudaFuncSetAttribute(attn_kernel,
                         cudaFuncAttributeMaxDynamicSharedMemorySize, 66560);

    // 1. RMSNorm + transpose
    rmsnorm_kernel<<<M_ROWS, 128>>>(x, norm_w, nullptr);

    // 2. QKV projection
    qkv_gemm_kernel<<<dim3(1536 / 64, M_ROWS / 64), 256>>>(wq, wk, wv);

    // 3. RoPE (+ q pre-scale)
    rope_kernel<<<(1024 * T_SEQ) / 4, 128>>>();

    // 4. causal attention + mask + residual + transpose
    attn_kernel<<<dim3(T_SEQ / 64, N_NEU * H_HEADS), 256, 66560>>>(pad);

    // 5. output projection
    out_gemm_kernel<<<dim3(512 / 64, M_ROWS / 64), 256>>>(wo, out);
}

// round 2
// speedup vs baseline: 2.6004x; 2.6004x over previous
#include <cuda_runtime.h>
#include <math.h>
#include <stdint.h>

// Problem constants
#define T_SEQ 384
#define N_NEU 128
#define D_MOD 512
#define H_HEADS 8
#define DHEAD 64
#define M_ROWS (N_NEU * T_SEQ)   // 49152
#define QKV_ELEMS (N_NEU * H_HEADS * T_SEQ * DHEAD)  // 25165824

// Scratch (device globals; allocation inside kernel_launch is forbidden)
__device__ float g_XN[N_NEU * T_SEQ * D_MOD];   // rmsnormed x, (n, t, d) layout
__device__ float g_Q[QKV_ELEMS];                // (r*8+h, t, dh)
__device__ float g_K[QKV_ELEMS];
__device__ float g_V[QKV_ELEMS];
__device__ float g_Y[M_ROWS * D_MOD];           // (t*128+n, d)

// ---------------------------------------------------------------------------
// Kernel 1: RMSNorm + transpose (t,n,d) -> (n,t,d)
// ---------------------------------------------------------------------------
__global__ void rmsnorm_kernel(const float* __restrict__ x,
                               const float* __restrict__ w) {
    int row = blockIdx.x;          // row = t*128 + n
    int t = row >> 7;
    int n = row & 127;
    int tid = threadIdx.x;

    float4 v = ((const float4*)(x + (size_t)row * D_MOD))[tid];
    float ss = v.x * v.x + v.y * v.y + v.z * v.z + v.w * v.w;
    #pragma unroll
    for (int m = 16; m; m >>= 1) ss += __shfl_xor_sync(0xffffffffu, ss, m);

    __shared__ float sbuf[4];
    if ((tid & 31) == 0) sbuf[tid >> 5] = ss;
    __syncthreads();
    float tot = sbuf[0] + sbuf[1] + sbuf[2] + sbuf[3];
    float inv = rsqrtf(tot * (1.0f / (float)D_MOD) + 1e-6f);

    float4 wv = ((const float4*)w)[tid];
    float4 o;
    o.x = v.x * inv * wv.x;
    o.y = v.y * inv * wv.y;
    o.z = v.z * inv * wv.z;
    o.w = v.w * inv * wv.w;
    ((float4*)(g_XN + ((size_t)n * T_SEQ + t) * D_MOD))[tid] = o;
}

// ---------------------------------------------------------------------------
// tf32 mma helpers
// ---------------------------------------------------------------------------
__device__ __forceinline__ uint32_t f2tf32(float f) {
    uint32_t r;
    asm("cvt.rna.tf32.f32 %0, %1;" : "=r"(r) : "f"(f));
    return r;
}

__device__ __forceinline__ void mma_tf32(float c[4], const uint32_t a[4],
                                         const uint32_t b[2]) {
    asm volatile(
        "mma.sync.aligned.m16n8k8.row.col.f32.tf32.tf32.f32 "
        "{%0,%1,%2,%3}, {%4,%5,%6,%7}, {%8,%9}, {%0,%1,%2,%3};"
        : "+f"(c[0]), "+f"(c[1]), "+f"(c[2]), "+f"(c[3])
        : "r"(a[0]), "r"(a[1]), "r"(a[2]), "r"(a[3]),
          "r"(b[0]), "r"(b[1]));
}

// Shared GEMM mainloop: C(128x128 tile) = A(128xK) * B(128xK)^T, K=512.
// smem stride 36 floats per row -> bank-conflict-free fragment loads.
#define SMS 36
#define SM_TILE_U (128 * SMS)

__device__ __forceinline__ void gemm_mainloop_tf32(
    const float* __restrict__ A, const float* __restrict__ B,
    int m0, int n0row,      // A row base, B row base (within a 512-row weight)
    uint32_t* __restrict__ As, uint32_t* __restrict__ Bs,
    float c[2][8][4], int tid)
{
    const int lane = tid & 31;
    const int warp = tid >> 5;
    const int wm = warp & 3;       // 4 warps along M (32 rows each)
    const int wn = warp >> 2;      // 2 warps along N (64 cols each)
    const int group = lane >> 2;   // 0..7
    const int qk = lane & 3;       // 0..3

    const int ldrow = tid >> 3;          // 0..31 -> actually 0..127 with i loop
    const int ldkq = (tid & 7) << 2;

    for (int kb = 0; kb < 512; kb += 32) {
        __syncthreads();
        #pragma unroll
        for (int i = 0; i < 4; i++) {
            int idx = tid + i * 256;
            int row = idx >> 3;          // 0..127
            int kq = (idx & 7) << 2;     // 0,4,...,28
            float4 a = *(const float4*)(A + (size_t)(m0 + row) * 512 + kb + kq);
            uint32_t* as = As + row * SMS + kq;
            as[0] = f2tf32(a.x); as[1] = f2tf32(a.y);
            as[2] = f2tf32(a.z); as[3] = f2tf32(a.w);
            float4 b = *(const float4*)(B + (size_t)(n0row + row) * 512 + kb + kq);
            uint32_t* bs = Bs + row * SMS + kq;
            bs[0] = f2tf32(b.x); bs[1] = f2tf32(b.y);
            bs[2] = f2tf32(b.z); bs[3] = f2tf32(b.w);
        }
        __syncthreads();

        #pragma unroll
        for (int ks = 0; ks < 4; ks++) {
            int k0 = ks * 8;
            uint32_t af[2][4];
            #pragma unroll
            for (int mt = 0; mt < 2; mt++) {
                int r0 = wm * 32 + mt * 16;
                af[mt][0] = As[(r0 + group) * SMS + k0 + qk];
                af[mt][1] = As[(r0 + 8 + group) * SMS + k0 + qk];
                af[mt][2] = As[(r0 + group) * SMS + k0 + 4 + qk];
                af[mt][3] = As[(r0 + 8 + group) * SMS + k0 + 4 + qk];
            }
            uint32_t bf[8][2];
            #pragma unroll
            for (int nt = 0; nt < 8; nt++) {
                int nr = wn * 64 + nt * 8;
                bf[nt][0] = Bs[(nr + group) * SMS + k0 + qk];
                bf[nt][1] = Bs[(nr + group) * SMS + k0 + 4 + qk];
            }
            #pragma unroll
            for (int mt = 0; mt < 2; mt++)
                #pragma unroll
                for (int nt = 0; nt < 8; nt++)
                    mma_tf32(c[mt][nt], af[mt], bf[nt]);
        }
    }
    (void)ldrow; (void)ldkq;
}

// ---------------------------------------------------------------------------
// Kernel 2: QKV projection with tf32 tensor cores.
// C[m][c] = sum_d XN[m][d] * W[c][d];  cols 0..511->Q, 512..1023->K, else V.
// Output scattered to (r*8+h, t, dh) layout.
// ---------------------------------------------------------------------------
__global__ void __launch_bounds__(256)
qkv_gemm_tc_kernel(const float* __restrict__ wq,
                   const float* __restrict__ wk,
                   const float* __restrict__ wv) {
    __shared__ uint32_t As[SM_TILE_U];
    __shared__ uint32_t Bs[SM_TILE_U];

    int n0 = blockIdx.x * 128;           // 0..1535 (tile within one weight)
    int m0 = blockIdx.y * 128;
    int which = n0 >> 9;
    int cc0 = n0 & 511;
    const float* W = (which == 0) ? wq : ((which == 1) ? wk : wv);
    float* Dst = (which == 0) ? g_Q : ((which == 1) ? g_K : g_V);

    int tid = threadIdx.x;
    float c[2][8][4] = {};
    gemm_mainloop_tf32(g_XN, W, m0, cc0, As, Bs, c, tid);

    const int lane = tid & 31;
    const int warp = tid >> 5;
    const int wm = warp & 3, wn = warp >> 2;
    const int group = lane >> 2, qk = lane & 3;

    #pragma unroll
    for (int mt = 0; mt < 2; mt++) {
        #pragma unroll
        for (int half = 0; half < 2; half++) {   // c0/c1 vs c2/c3
            int m = m0 + wm * 32 + mt * 16 + group + half * 8;
            int r = m / T_SEQ;
            int t = m - r * T_SEQ;
            #pragma unroll
            for (int nt = 0; nt < 8; nt++) {
                int col = wn * 64 + nt * 8 + qk * 2;     // within 128-tile
                int cc = cc0 + col;                       // within weight
                int h = cc >> 6, dh = cc & 63;
                float2 v;
                v.x = c[mt][nt][half * 2 + 0];
                v.y = c[mt][nt][half * 2 + 1];
                *(float2*)(Dst + (((size_t)(r * H_HEADS + h) * T_SEQ) + t) * DHEAD + dh) = v;
            }
        }
    }
}

// ---------------------------------------------------------------------------
// Kernel 3: RoPE on Q and K + q pre-scale by 1/8.
// ---------------------------------------------------------------------------
__global__ void rope_kernel() {
    int warp = (blockIdx.x << 2) + (threadIdx.x >> 5);
    int lane = threadIdx.x & 31;
    int rh = warp / T_SEQ;
    int t = warp - rh * T_SEQ;
    size_t base = ((size_t)rh * T_SEQ + t) * DHEAD;

    if (lane < 16) {
        int i = lane;
        float invf = __expf(-(float)i * (9.210340371976184f / 16.0f));
        float ang = (float)t * invf;
        float s = sinf(ang), c = cosf(ang);

        float qa = g_Q[base + 2 * i], qb = g_Q[base + 2 * i + 1];
        g_Q[base + 2 * i]     = (qa * c - qb * s) * 0.125f;
        g_Q[base + 2 * i + 1] = (qa * s + qb * c) * 0.125f;

        float ka = g_K[base + 2 * i], kb = g_K[base + 2 * i + 1];
        g_K[base + 2 * i]     = ka * c - kb * s;
        g_K[base + 2 * i + 1] = ka * s + kb * c;
    } else {
        int j = lane - 16;
        int d = 32 + 2 * j;
        g_Q[base + d]     *= 0.125f;
        g_Q[base + d + 1] *= 0.125f;
    }
}

// ---------------------------------------------------------------------------
// Kernel 4: causal flash attention (fp32 SIMT, unchanged this round).
// ---------------------------------------------------------------------------
__global__ void attn_kernel(const int* __restrict__ pad_mask) {
    extern __shared__ float sm[];
    float (*Qs)[65] = (float (*)[65])(sm);
    float (*Ks)[65] = (float (*)[65])(sm + 64 * 65);
    float (*Vs)[65] = (float (*)[65])(sm + 2 * 64 * 65);
    float (*Ps)[65] = (float (*)[65])(sm + 3 * 64 * 65);

    int qt = blockIdx.x;
    int rh = blockIdx.y;
    int r = rh >> 3, h = rh & 7;
    int qbase = qt * 64;

    int tid = threadIdx.x;
    int ty = tid >> 4, tx = tid & 15;
    int qr0 = ty * 4;
    int kc0 = tx * 4;
    int dh0 = tx * 4;

    const float* Qp = g_Q + ((size_t)rh * T_SEQ + qbase) * DHEAD;
    for (int f = tid; f < 64 * 16; f += 256) {
        int row = f >> 4, c4 = (f & 15) << 2;
        float4 v = *(const float4*)(Qp + row * DHEAD + c4);
        Qs[row][c4] = v.x; Qs[row][c4 + 1] = v.y;
        Qs[row][c4 + 2] = v.z; Qs[row][c4 + 3] = v.w;
    }

    float o[4][4] = {};
    float mrow[4] = {-1e30f, -1e30f, -1e30f, -1e30f};
    float lrow[4] = {0.f, 0.f, 0.f, 0.f};

    int ntiles = qt + 1;
    for (int kt = 0; kt < ntiles; kt++) {
        int kbase = kt * 64;
        __syncthreads();
        const float* Kp = g_K + ((size_t)rh * T_SEQ + kbase) * DHEAD;
        const float* Vp = g_V + ((size_t)rh * T_SEQ + kbase) * DHEAD;
        for (int f = tid; f < 64 * 16; f += 256) {
            int row = f >> 4, c4 = (f & 15) << 2;
            float4 kv = *(const float4*)(Kp + row * DHEAD + c4);
            Ks[row][c4] = kv.x; Ks[row][c4 + 1] = kv.y;
            Ks[row][c4 + 2] = kv.z; Ks[row][c4 + 3] = kv.w;
            float4 vv = *(const float4*)(Vp + row * DHEAD + c4);
            Vs[row][c4] = vv.x; Vs[row][c4 + 1] = vv.y;
            Vs[row][c4 + 2] = vv.z; Vs[row][c4 + 3] = vv.w;
        }
        __syncthreads();

        float s[4][4] = {};
        #pragma unroll
        for (int d = 0; d < 64; d++) {
            float qa[4], kb[4];
            #pragma unroll
            for (int i = 0; i < 4; i++) qa[i] = Qs[qr0 + i][d];
            #pragma unroll
            for (int j = 0; j < 4; j++) kb[j] = Ks[kc0 + j][d];
            #pragma unroll
            for (int i = 0; i < 4; i++)
                #pragma unroll
                for (int j = 0; j < 4; j++) s[i][j] += qa[i] * kb[j];
        }

        #pragma unroll
        for (int i = 0; i < 4; i++) {
            int tq = qbase + qr0 + i;
            float tmax = -1e30f;
            #pragma unroll
            for (int j = 0; j < 4; j++) {
                bool ok = (kbase + kc0 + j) <= tq;
                s[i][j] = ok ? s[i][j] : -1e30f;
                tmax = fmaxf(tmax, s[i][j]);
            }
            #pragma unroll
            for (int msk = 1; msk < 16; msk <<= 1)
                tmax = fmaxf(tmax, __shfl_xor_sync(0xffffffffu, tmax, msk));
            float nm = fmaxf(mrow[i], tmax);
            float scl = __expf(mrow[i] - nm);
            float ts = 0.f;
            #pragma unroll
            for (int j = 0; j < 4; j++) {
                float p = __expf(s[i][j] - nm);
                s[i][j] = p;
                ts += p;
            }
            #pragma unroll
            for (int msk = 1; msk < 16; msk <<= 1)
                ts += __shfl_xor_sync(0xffffffffu, ts, msk);
            lrow[i] = lrow[i] * scl + ts;
            mrow[i] = nm;
            #pragma unroll
            for (int j = 0; j < 4; j++) o[i][j] *= scl;
        }

        #pragma unroll
        for (int i = 0; i < 4; i++)
            #pragma unroll
            for (int j = 0; j < 4; j++) Ps[qr0 + i][kc0 + j] = s[i][j];
        __syncthreads();

        #pragma unroll
        for (int kc = 0; kc < 64; kc++) {
            float pa[4], vb[4];
            #pragma unroll
            for (int i = 0; i < 4; i++) pa[i] = Ps[qr0 + i][kc];
            #pragma unroll
            for (int j = 0; j < 4; j++) vb[j] = Vs[kc][dh0 + j];
            #pragma unroll
            for (int i = 0; i < 4; i++)
                #pragma unroll
                for (int j = 0; j < 4; j++) o[i][j] += pa[i] * vb[j];
        }
    }

    bool valid = (pad_mask[r] != 0);
    #pragma unroll
    for (int i = 0; i < 4; i++) {
        int tq = qbase + qr0 + i;
        float invl = 1.0f / lrow[i];
        const float* xr = g_XN + ((size_t)r * T_SEQ + tq) * D_MOD + h * DHEAD + dh0;
        float* yp = g_Y + ((size_t)tq * N_NEU + r) * D_MOD + h * DHEAD + dh0;
        float4 res = *(const float4*)xr;
        float4 ov;
        ov.x = (valid ? o[i][0] * invl : 0.f) + res.x;
        ov.y = (valid ? o[i][1] * invl : 0.f) + res.y;
        ov.z = (valid ? o[i][2] * invl : 0.f) + res.z;
        ov.w = (valid ? o[i][3] * invl : 0.f) + res.w;
        *(float4*)yp = ov;
    }
}

// ---------------------------------------------------------------------------
// Kernel 5: output projection with tf32 tensor cores.
// out[m][c] = sum_d Y[m][d] * wo[c][d].  M=49152, N=512.
// ---------------------------------------------------------------------------
__global__ void __launch_bounds__(256)
out_gemm_tc_kernel(const float* __restrict__ wo,
                   float* __restrict__ out) {
    __shared__ uint32_t As[SM_TILE_U];
    __shared__ uint32_t Bs[SM_TILE_U];

    int n0 = blockIdx.x * 128;
    int m0 = blockIdx.y * 128;
    int tid = threadIdx.x;

    float c[2][8][4] = {};
    gemm_mainloop_tf32(g_Y, wo, m0, n0, As, Bs, c, tid);

    const int lane = tid & 31;
    const int warp = tid >> 5;
    const int wm = warp & 3, wn = warp >> 2;
    const int group = lane >> 2, qk = lane & 3;

    #pragma unroll
    for (int mt = 0; mt < 2; mt++) {
        #pragma unroll
        for (int half = 0; half < 2; half++) {
            int m = m0 + wm * 32 + mt * 16 + group + half * 8;
            #pragma unroll
            for (int nt = 0; nt < 8; nt++) {
                int col = n0 + wn * 64 + nt * 8 + qk * 2;
                float2 v;
                v.x = c[mt][nt][half * 2 + 0];
                v.y = c[mt][nt][half * 2 + 1];
                *(float2*)(out + (size_t)m * 512 + col) = v;
            }
        }
    }
}

// ---------------------------------------------------------------------------
extern "C" void kernel_launch(void* const* d_in, const int* in_sizes, int n_in,
                              void* d_out, int out_size) {
    const float* x       = (const float*)d_in[0];
    const int*   pad     = (const int*)d_in[1];
    const float* norm_w  = (const float*)d_in[2];
    const float* wq      = (const float*)d_in[3];
    const float* wk      = (const float*)d_in[4];
    const float* wv      = (const float*)d_in[5];
    const float* wo      = (const float*)d_in[6];
    float* out = (float*)d_out;
    (void)in_sizes; (void)n_in; (void)out_size;

    cudaFuncSetAttribute(attn_kernel,
                         cudaFuncAttributeMaxDynamicSharedMemorySize, 66560);

    // 1. RMSNorm + transpose
    rmsnorm_kernel<<<M_ROWS, 128>>>(x, norm_w);

    // 2. QKV projection (tf32 tensor cores)
    qkv_gemm_tc_kernel<<<dim3(1536 / 128, M_ROWS / 128), 256>>>(wq, wk, wv);

    // 3. RoPE (+ q pre-scale)
    rope_kernel<<<(1024 * T_SEQ) / 4, 128>>>();

    // 4. causal attention + mask + residual + transpose
    attn_kernel<<<dim3(T_SEQ / 64, N_NEU * H_HEADS), 256, 66560>>>(pad);

    // 5. output projection (tf32 tensor cores)
    out_gemm_tc_kernel<<<dim3(512 / 128, M_ROWS / 128), 256>>>(wo, out);
}

// round 3
// speedup vs baseline: 3.7727x; 1.4508x over previous
#include <cuda_runtime.h>
#include <math.h>
#include <stdint.h>

// Problem constants
#define T_SEQ 384
#define N_NEU 128
#define D_MOD 512
#define H_HEADS 8
#define DHEAD 64
#define M_ROWS (N_NEU * T_SEQ)   // 49152
#define QKV_ELEMS (N_NEU * H_HEADS * T_SEQ * DHEAD)  // 25165824

// Scratch (device globals; allocation inside kernel_launch is forbidden)
__device__ float g_XN[N_NEU * T_SEQ * D_MOD];   // rmsnormed x, (n, t, d) layout
__device__ float g_Q[QKV_ELEMS];                // (r*8+h, t, dh), rope+scale applied
__device__ float g_K[QKV_ELEMS];                // rope applied
__device__ float g_V[QKV_ELEMS];
__device__ float g_Y[M_ROWS * D_MOD];           // (t*128+n, d)

// ---------------------------------------------------------------------------
// Kernel 1: RMSNorm + transpose (t,n,d) -> (n,t,d)
// ---------------------------------------------------------------------------
__global__ void rmsnorm_kernel(const float* __restrict__ x,
                               const float* __restrict__ w) {
    int row = blockIdx.x;          // row = t*128 + n
    int t = row >> 7;
    int n = row & 127;
    int tid = threadIdx.x;

    float4 v = ((const float4*)(x + (size_t)row * D_MOD))[tid];
    float ss = v.x * v.x + v.y * v.y + v.z * v.z + v.w * v.w;
    #pragma unroll
    for (int m = 16; m; m >>= 1) ss += __shfl_xor_sync(0xffffffffu, ss, m);

    __shared__ float sbuf[4];
    if ((tid & 31) == 0) sbuf[tid >> 5] = ss;
    __syncthreads();
    float tot = sbuf[0] + sbuf[1] + sbuf[2] + sbuf[3];
    float inv = rsqrtf(tot * (1.0f / (float)D_MOD) + 1e-6f);

    float4 wv = ((const float4*)w)[tid];
    float4 o;
    o.x = v.x * inv * wv.x;
    o.y = v.y * inv * wv.y;
    o.z = v.z * inv * wv.z;
    o.w = v.w * inv * wv.w;
    ((float4*)(g_XN + ((size_t)n * T_SEQ + t) * D_MOD))[tid] = o;
}

// ---------------------------------------------------------------------------
// tf32 mma helpers
// ---------------------------------------------------------------------------
__device__ __forceinline__ uint32_t f2tf32(float f) {
    uint32_t r;
    asm("cvt.rna.tf32.f32 %0, %1;" : "=r"(r) : "f"(f));
    return r;
}

__device__ __forceinline__ void mma_tf32(float c[4], const uint32_t a[4],
                                         const uint32_t b[2]) {
    asm volatile(
        "mma.sync.aligned.m16n8k8.row.col.f32.tf32.tf32.f32 "
        "{%0,%1,%2,%3}, {%4,%5,%6,%7}, {%8,%9}, {%0,%1,%2,%3};"
        : "+f"(c[0]), "+f"(c[1]), "+f"(c[2]), "+f"(c[3])
        : "r"(a[0]), "r"(a[1]), "r"(a[2]), "r"(a[3]),
          "r"(b[0]), "r"(b[1]));
}

// Shared GEMM mainloop: C(128x128 tile) = A(128xK) * B(128xK)^T, K=512.
#define SMS 36
#define SM_TILE_U (128 * SMS)

__device__ __forceinline__ void gemm_mainloop_tf32(
    const float* __restrict__ A, const float* __restrict__ B,
    int m0, int n0row,
    uint32_t* __restrict__ As, uint32_t* __restrict__ Bs,
    float c[2][8][4], int tid)
{
    const int lane = tid & 31;
    const int warp = tid >> 5;
    const int wm = warp & 3;
    const int wn = warp >> 2;
    const int group = lane >> 2;
    const int qk = lane & 3;

    for (int kb = 0; kb < 512; kb += 32) {
        __syncthreads();
        #pragma unroll
        for (int i = 0; i < 4; i++) {
            int idx = tid + i * 256;
            int row = idx >> 3;
            int kq = (idx & 7) << 2;
            float4 a = *(const float4*)(A + (size_t)(m0 + row) * 512 + kb + kq);
            uint32_t* as = As + row * SMS + kq;
            as[0] = f2tf32(a.x); as[1] = f2tf32(a.y);
            as[2] = f2tf32(a.z); as[3] = f2tf32(a.w);
            float4 b = *(const float4*)(B + (size_t)(n0row + row) * 512 + kb + kq);
            uint32_t* bs = Bs + row * SMS + kq;
            bs[0] = f2tf32(b.x); bs[1] = f2tf32(b.y);
            bs[2] = f2tf32(b.z); bs[3] = f2tf32(b.w);
        }
        __syncthreads();

        #pragma unroll
        for (int ks = 0; ks < 4; ks++) {
            int k0 = ks * 8;
            uint32_t af[2][4];
            #pragma unroll
            for (int mt = 0; mt < 2; mt++) {
                int r0 = wm * 32 + mt * 16;
                af[mt][0] = As[(r0 + group) * SMS + k0 + qk];
                af[mt][1] = As[(r0 + 8 + group) * SMS + k0 + qk];
                af[mt][2] = As[(r0 + group) * SMS + k0 + 4 + qk];
                af[mt][3] = As[(r0 + 8 + group) * SMS + k0 + 4 + qk];
            }
            uint32_t bf[8][2];
            #pragma unroll
            for (int nt = 0; nt < 8; nt++) {
                int nr = wn * 64 + nt * 8;
                bf[nt][0] = Bs[(nr + group) * SMS + k0 + qk];
                bf[nt][1] = Bs[(nr + group) * SMS + k0 + 4 + qk];
            }
            #pragma unroll
            for (int mt = 0; mt < 2; mt++)
                #pragma unroll
                for (int nt = 0; nt < 8; nt++)
                    mma_tf32(c[mt][nt], af[mt], bf[nt]);
        }
    }
}

// ---------------------------------------------------------------------------
// Kernel 2: QKV projection (tf32 TC) with FUSED RoPE + q-scale epilogue.
// ---------------------------------------------------------------------------
__global__ void __launch_bounds__(256)
qkv_gemm_tc_kernel(const float* __restrict__ wq,
                   const float* __restrict__ wk,
                   const float* __restrict__ wv) {
    __shared__ uint32_t As[SM_TILE_U];
    __shared__ uint32_t Bs[SM_TILE_U];

    int n0 = blockIdx.x * 128;
    int m0 = blockIdx.y * 128;
    int which = n0 >> 9;                 // 0=Q, 1=K, 2=V
    int cc0 = n0 & 511;
    const float* W = (which == 0) ? wq : ((which == 1) ? wk : wv);
    float* Dst = (which == 0) ? g_Q : ((which == 1) ? g_K : g_V);

    int tid = threadIdx.x;
    float c[2][8][4] = {};
    gemm_mainloop_tf32(g_XN, W, m0, cc0, As, Bs, c, tid);

    const int lane = tid & 31;
    const int warp = tid >> 5;
    const int wm = warp & 3, wn = warp >> 2;
    const int group = lane >> 2, qk = lane & 3;

    #pragma unroll
    for (int mt = 0; mt < 2; mt++) {
        #pragma unroll
        for (int half = 0; half < 2; half++) {
            int m = m0 + wm * 32 + mt * 16 + group + half * 8;
            int r = m / T_SEQ;
            int t = m - r * T_SEQ;
            #pragma unroll
            for (int nt = 0; nt < 8; nt++) {
                int col = wn * 64 + nt * 8 + qk * 2;
                int cc = cc0 + col;
                int h = cc >> 6, dh = cc & 63;
                float2 v;
                v.x = c[mt][nt][half * 2 + 0];
                v.y = c[mt][nt][half * 2 + 1];
                // fused RoPE (interleaved pairs, rotary dim 32) for Q,K
                if (which <= 1 && dh < 32) {
                    int i = dh >> 1;
                    float invf = __expf(-(float)i * 0.57564627324851142f); // ln(1e4)/16
                    float sn, cs;
                    sincosf((float)t * invf, &sn, &cs);
                    float a = v.x, b = v.y;
                    v.x = a * cs - b * sn;
                    v.y = a * sn + b * cs;
                }
                if (which == 0) { v.x *= 0.125f; v.y *= 0.125f; }
                *(float2*)(Dst + (((size_t)(r * H_HEADS + h) * T_SEQ) + t) * DHEAD + dh) = v;
            }
        }
    }
}

// ---------------------------------------------------------------------------
// Kernel 3: tensor-core causal flash attention.
// One block per (q-tile of 128 rows, rh). 8 warps; warp w owns q rows
// [w*16, w*16+16). KV tiles of 64. S and PV via mma.m16n8k8.tf32.
// smem strides of 68 make all fragment LDS bank-conflict-free.
// Fused epilogue: 1/l, pad mask, residual add, (t,n,d) scatter.
// ---------------------------------------------------------------------------
#define ATT_STR 68
#define ATT_SMEM_WORDS ((128 + 64 + 64 + 128) * ATT_STR)   // 26112 words = 104448 B

__global__ void __launch_bounds__(256)
attn_tc_kernel(const int* __restrict__ pad_mask) {
    extern __shared__ uint32_t smu[];
    uint32_t* Qs = smu;                       // [128][68] tf32
    uint32_t* Ks = Qs + 128 * ATT_STR;        // [64][68]  tf32 (row=kv, col=d)
    uint32_t* Vs = Ks + 64 * ATT_STR;         // [64][68]  tf32 (row=kv, col=dh)
    uint32_t* Ps = Vs + 64 * ATT_STR;         // [128][68] tf32

    const int qt = blockIdx.x;
    const int rh = blockIdx.y;
    const int r = rh >> 3, h = rh & 7;
    const int qbase = qt * 128;

    const int tid = threadIdx.x;
    const int warp = tid >> 5;
    const int lane = tid & 31;
    const int g = lane >> 2;
    const int qk = lane & 3;
    const int wrow = warp * 16;              // warp's local q-row base

    // load Q tile (128 x 64) -> tf32 smem
    const float* Qp = g_Q + ((size_t)rh * T_SEQ + qbase) * DHEAD;
    #pragma unroll
    for (int i = 0; i < 8; i++) {
        int idx = tid + i * 256;
        int row = idx >> 4, c4 = (idx & 15) << 2;
        float4 v = *(const float4*)(Qp + row * DHEAD + c4);
        uint32_t* qs = Qs + row * ATT_STR + c4;
        qs[0] = f2tf32(v.x); qs[1] = f2tf32(v.y);
        qs[2] = f2tf32(v.z); qs[3] = f2tf32(v.w);
    }

    float o[8][4] = {};
    float m0r = -1e30f, m1r = -1e30f;
    float l0r = 0.f, l1r = 0.f;

    const int ntiles = 2 * qt + 2;
    for (int kt = 0; kt < ntiles; kt++) {
        const int kbase = kt * 64;
        __syncthreads();
        const float* Kp = g_K + ((size_t)rh * T_SEQ + kbase) * DHEAD;
        const float* Vp = g_V + ((size_t)rh * T_SEQ + kbase) * DHEAD;
        #pragma unroll
        for (int i = 0; i < 4; i++) {
            int idx = tid + i * 256;
            int row = idx >> 4, c4 = (idx & 15) << 2;
            float4 kv = *(const float4*)(Kp + row * DHEAD + c4);
            uint32_t* ks = Ks + row * ATT_STR + c4;
            ks[0] = f2tf32(kv.x); ks[1] = f2tf32(kv.y);
            ks[2] = f2tf32(kv.z); ks[3] = f2tf32(kv.w);
            float4 vv = *(const float4*)(Vp + row * DHEAD + c4);
            uint32_t* vs = Vs + row * ATT_STR + c4;
            vs[0] = f2tf32(vv.x); vs[1] = f2tf32(vv.y);
            vs[2] = f2tf32(vv.z); vs[3] = f2tf32(vv.w);
        }
        __syncthreads();

        // warp inactive if all its rows are above this kv tile (fully masked)
        if (kbase > qbase + wrow + 15) continue;

        // ---- S = Q K^T ----
        float s[8][4] = {};
        #pragma unroll
        for (int ks8 = 0; ks8 < 8; ks8++) {
            int k0 = ks8 * 8;
            uint32_t af[4];
            af[0] = Qs[(wrow + g) * ATT_STR + k0 + qk];
            af[1] = Qs[(wrow + 8 + g) * ATT_STR + k0 + qk];
            af[2] = Qs[(wrow + g) * ATT_STR + k0 + 4 + qk];
            af[3] = Qs[(wrow + 8 + g) * ATT_STR + k0 + 4 + qk];
            #pragma unroll
            for (int nt = 0; nt < 8; nt++) {
                uint32_t bf[2];
                bf[0] = Ks[(nt * 8 + g) * ATT_STR + k0 + qk];
                bf[1] = Ks[(nt * 8 + g) * ATT_STR + k0 + 4 + qk];
                mma_tf32(s[nt], af, bf);
            }
        }

        const int row0 = qbase + wrow + g;
        const int row1 = row0 + 8;

        // ---- causal mask (only the two diagonal tiles need it) ----
        if (kt >= 2 * qt) {
            #pragma unroll
            for (int nt = 0; nt < 8; nt++) {
                int c0 = kbase + nt * 8 + 2 * qk;
                if (c0 > row0)     s[nt][0] = -1e30f;
                if (c0 + 1 > row0) s[nt][1] = -1e30f;
                if (c0 > row1)     s[nt][2] = -1e30f;
                if (c0 + 1 > row1) s[nt][3] = -1e30f;
            }
        }

        // ---- online softmax (rows live in quad: lanes g*4+{0..3}) ----
        float tmax0 = -1e30f, tmax1 = -1e30f;
        #pragma unroll
        for (int nt = 0; nt < 8; nt++) {
            tmax0 = fmaxf(tmax0, fmaxf(s[nt][0], s[nt][1]));
            tmax1 = fmaxf(tmax1, fmaxf(s[nt][2], s[nt][3]));
        }
        tmax0 = fmaxf(tmax0, __shfl_xor_sync(0xffffffffu, tmax0, 1));
        tmax0 = fmaxf(tmax0, __shfl_xor_sync(0xffffffffu, tmax0, 2));
        tmax1 = fmaxf(tmax1, __shfl_xor_sync(0xffffffffu, tmax1, 1));
        tmax1 = fmaxf(tmax1, __shfl_xor_sync(0xffffffffu, tmax1, 2));

        float nm0 = fmaxf(m0r, tmax0), nm1 = fmaxf(m1r, tmax1);
        float scl0 = __expf(m0r - nm0), scl1 = __expf(m1r - nm1);
        float ts0 = 0.f, ts1 = 0.f;
        #pragma unroll
        for (int nt = 0; nt < 8; nt++) {
            s[nt][0] = __expf(s[nt][0] - nm0);
            s[nt][1] = __expf(s[nt][1] - nm0);
            s[nt][2] = __expf(s[nt][2] - nm1);
            s[nt][3] = __expf(s[nt][3] - nm1);
            ts0 += s[nt][0] + s[nt][1];
            ts1 += s[nt][2] + s[nt][3];
        }
        ts0 += __shfl_xor_sync(0xffffffffu, ts0, 1);
        ts0 += __shfl_xor_sync(0xffffffffu, ts0, 2);
        ts1 += __shfl_xor_sync(0xffffffffu, ts1, 1);
        ts1 += __shfl_xor_sync(0xffffffffu, ts1, 2);
        l0r = l0r * scl0 + ts0;
        l1r = l1r * scl1 + ts1;
        m0r = nm0; m1r = nm1;
        #pragma unroll
        for (int nt = 0; nt < 8; nt++) {
            o[nt][0] *= scl0; o[nt][1] *= scl0;
            o[nt][2] *= scl1; o[nt][3] *= scl1;
        }

        // ---- P -> smem (tf32), same-warp consumption ----
        #pragma unroll
        for (int nt = 0; nt < 8; nt++) {
            uint32_t* p0 = Ps + (wrow + g) * ATT_STR + nt * 8 + 2 * qk;
            *(uint2*)p0 = make_uint2(f2tf32(s[nt][0]), f2tf32(s[nt][1]));
            uint32_t* p1 = Ps + (wrow + 8 + g) * ATT_STR + nt * 8 + 2 * qk;
            *(uint2*)p1 = make_uint2(f2tf32(s[nt][2]), f2tf32(s[nt][3]));
        }
        __syncwarp();

        // ---- O += P @ V ----
        #pragma unroll
        for (int ks8 = 0; ks8 < 8; ks8++) {
            int k0 = ks8 * 8;
            uint32_t af[4];
            af[0] = Ps[(wrow + g) * ATT_STR + k0 + qk];
            af[1] = Ps[(wrow + 8 + g) * ATT_STR + k0 + qk];
            af[2] = Ps[(wrow + g) * ATT_STR + k0 + 4 + qk];
            af[3] = Ps[(wrow + 8 + g) * ATT_STR + k0 + 4 + qk];
            #pragma unroll
            for (int nt = 0; nt < 8; nt++) {
                uint32_t bf[2];
                bf[0] = Vs[(k0 + qk) * ATT_STR + nt * 8 + g];
                bf[1] = Vs[(k0 + 4 + qk) * ATT_STR + nt * 8 + g];
                mma_tf32(o[nt], af, bf);
            }
        }
    }

    // ---- epilogue: normalize, pad mask, residual, scatter (t,n,d) ----
    const bool valid = (pad_mask[r] != 0);
    const float inv0 = 1.0f / l0r, inv1 = 1.0f / l1r;
    const int t0 = qbase + wrow + g;
    const int t1 = t0 + 8;
    #pragma unroll
    for (int nt = 0; nt < 8; nt++) {
        int dh = nt * 8 + 2 * qk;
        const float* xr0 = g_XN + ((size_t)r * T_SEQ + t0) * D_MOD + h * DHEAD + dh;
        float* yp0 = g_Y + ((size_t)t0 * N_NEU + r) * D_MOD + h * DHEAD + dh;
        float2 res0 = *(const float2*)xr0;
        float2 ov0;
        ov0.x = (valid ? o[nt][0] * inv0 : 0.f) + res0.x;
        ov0.y = (valid ? o[nt][1] * inv0 : 0.f) + res0.y;
        *(float2*)yp0 = ov0;

        const float* xr1 = g_XN + ((size_t)r * T_SEQ + t1) * D_MOD + h * DHEAD + dh;
        float* yp1 = g_Y + ((size_t)t1 * N_NEU + r) * D_MOD + h * DHEAD + dh;
        float2 res1 = *(const float2*)xr1;
        float2 ov1;
        ov1.x = (valid ? o[nt][2] * inv1 : 0.f) + res1.x;
        ov1.y = (valid ? o[nt][3] * inv1 : 0.f) + res1.y;
        *(float2*)yp1 = ov1;
    }
}

// ---------------------------------------------------------------------------
// Kernel 4: output projection (tf32 TC).
// ---------------------------------------------------------------------------
__global__ void __launch_bounds__(256)
out_gemm_tc_kernel(const float* __restrict__ wo,
                   float* __restrict__ out) {
    __shared__ uint32_t As[SM_TILE_U];
    __shared__ uint32_t Bs[SM_TILE_U];

    int n0 = blockIdx.x * 128;
    int m0 = blockIdx.y * 128;
    int tid = threadIdx.x;

    float c[2][8][4] = {};
    gemm_mainloop_tf32(g_Y, wo, m0, n0, As, Bs, c, tid);

    const int lane = tid & 31;
    const int warp = tid >> 5;
    const int wm = warp & 3, wn = warp >> 2;
    const int group = lane >> 2, qk = lane & 3;

    #pragma unroll
    for (int mt = 0; mt < 2; mt++) {
        #pragma unroll
        for (int half = 0; half < 2; half++) {
            int m = m0 + wm * 32 + mt * 16 + group + half * 8;
            #pragma unroll
            for (int nt = 0; nt < 8; nt++) {
                int col = n0 + wn * 64 + nt * 8 + qk * 2;
                float2 v;
                v.x = c[mt][nt][half * 2 + 0];
                v.y = c[mt][nt][half * 2 + 1];
                *(float2*)(out + (size_t)m * 512 + col) = v;
            }
        }
    }
}

// ---------------------------------------------------------------------------
extern "C" void kernel_launch(void* const* d_in, const int* in_sizes, int n_in,
                              void* d_out, int out_size) {
    const float* x       = (const float*)d_in[0];
    const int*   pad     = (const int*)d_in[1];
    const float* norm_w  = (const float*)d_in[2];
    const float* wq      = (const float*)d_in[3];
    const float* wk      = (const float*)d_in[4];
    const float* wv      = (const float*)d_in[5];
    const float* wo      = (const float*)d_in[6];
    float* out = (float*)d_out;
    (void)in_sizes; (void)n_in; (void)out_size;

    cudaFuncSetAttribute(attn_tc_kernel,
                         cudaFuncAttributeMaxDynamicSharedMemorySize,
                         ATT_SMEM_WORDS * 4);

    // 1. RMSNorm + transpose
    rmsnorm_kernel<<<M_ROWS, 128>>>(x, norm_w);

    // 2. QKV projection (tf32 TC) + fused RoPE/scale
    qkv_gemm_tc_kernel<<<dim3(1536 / 128, M_ROWS / 128), 256>>>(wq, wk, wv);

    // 3. tensor-core causal attention + mask + residual + transpose
    attn_tc_kernel<<<dim3(T_SEQ / 128, N_NEU * H_HEADS), 256,
                     ATT_SMEM_WORDS * 4>>>(pad);

    // 4. output projection (tf32 TC)
    out_gemm_tc_kernel<<<dim3(512 / 128, M_ROWS / 128), 256>>>(wo, out);
}

// round 4
// speedup vs baseline: 3.9871x; 1.0568x over previous
#include <cuda_runtime.h>
#include <math.h>
#include <stdint.h>

// Problem constants
#define T_SEQ 384
#define N_NEU 128
#define D_MOD 512
#define H_HEADS 8
#define DHEAD 64
#define M_ROWS (N_NEU * T_SEQ)   // 49152
#define QKV_ELEMS (N_NEU * H_HEADS * T_SEQ * DHEAD)  // 25165824

// Scratch (device globals; allocation inside kernel_launch is forbidden)
__device__ float g_XN[N_NEU * T_SEQ * D_MOD];   // rmsnormed x, (n, t, d) layout
__device__ float g_Q[QKV_ELEMS];                // (r*8+h, t, dh), rope+scale applied
__device__ float g_K[QKV_ELEMS];                // rope applied
__device__ float g_V[QKV_ELEMS];
__device__ float g_Y[M_ROWS * D_MOD];           // (t*128+n, d)

// ---------------------------------------------------------------------------
// Kernel 1: RMSNorm + transpose (t,n,d) -> (n,t,d)
// ---------------------------------------------------------------------------
__global__ void rmsnorm_kernel(const float* __restrict__ x,
                               const float* __restrict__ w) {
    int row = blockIdx.x;          // row = t*128 + n
    int t = row >> 7;
    int n = row & 127;
    int tid = threadIdx.x;

    float4 v = ((const float4*)(x + (size_t)row * D_MOD))[tid];
    float ss = v.x * v.x + v.y * v.y + v.z * v.z + v.w * v.w;
    #pragma unroll
    for (int m = 16; m; m >>= 1) ss += __shfl_xor_sync(0xffffffffu, ss, m);

    __shared__ float sbuf[4];
    if ((tid & 31) == 0) sbuf[tid >> 5] = ss;
    __syncthreads();
    float tot = sbuf[0] + sbuf[1] + sbuf[2] + sbuf[3];
    float inv = rsqrtf(tot * (1.0f / (float)D_MOD) + 1e-6f);

    float4 wv = ((const float4*)w)[tid];
    float4 o;
    o.x = v.x * inv * wv.x;
    o.y = v.y * inv * wv.y;
    o.z = v.z * inv * wv.z;
    o.w = v.w * inv * wv.w;
    ((float4*)(g_XN + ((size_t)n * T_SEQ + t) * D_MOD))[tid] = o;
}

// ---------------------------------------------------------------------------
// helpers
// ---------------------------------------------------------------------------
__device__ __forceinline__ uint32_t f2tf32(float f) {
    uint32_t r;
    asm("cvt.rna.tf32.f32 %0, %1;" : "=r"(r) : "f"(f));
    return r;
}

__device__ __forceinline__ void mma_tf32(float c[4], const uint32_t a[4],
                                         const uint32_t b[2]) {
    asm volatile(
        "mma.sync.aligned.m16n8k8.row.col.f32.tf32.tf32.f32 "
        "{%0,%1,%2,%3}, {%4,%5,%6,%7}, {%8,%9}, {%0,%1,%2,%3};"
        : "+f"(c[0]), "+f"(c[1]), "+f"(c[2]), "+f"(c[3])
        : "r"(a[0]), "r"(a[1]), "r"(a[2]), "r"(a[3]),
          "r"(b[0]), "r"(b[1]));
}

__device__ __forceinline__ uint32_t smem_u32(const void* p) {
    return (uint32_t)__cvta_generic_to_shared(p);
}
#define CP_ASYNC16(dst, src) \
    asm volatile("cp.async.cg.shared.global [%0], [%1], 16;" \
                 :: "r"(dst), "l"(src))
#define CP_COMMIT() asm volatile("cp.async.commit_group;" ::: "memory")
#define CP_WAIT0()  asm volatile("cp.async.wait_group 0;" ::: "memory")

// ---------------------------------------------------------------------------
// GEMM mainloop: C(128x128) = A(128xK) * B(128xK)^T, K=512.
// cp.async double-buffered (2 stages, K-chunk 32), fp32 in smem, cvt at lds.
// smem stride 36 floats -> conflict-free fragment loads.
// dynamic smem: 2 stages x (A 128x36 + B 128x36) floats = 73728 B.
// ---------------------------------------------------------------------------
#define SMS 36
#define GEMM_STAGE_FLT (2 * 128 * SMS)          // 9216 floats per stage (A+B)
#define GEMM_SMEM_BYTES (2 * GEMM_STAGE_FLT * 4)

__device__ __forceinline__ void gemm_mainloop_tf32(
    const float* __restrict__ A, const float* __restrict__ B,
    int m0, int n0row, float* __restrict__ sm,
    float c[2][8][4], int tid)
{
    const int lane = tid & 31;
    const int warp = tid >> 5;
    const int wm = warp & 3;
    const int wn = warp >> 2;
    const int group = lane >> 2;
    const int qk = lane & 3;

    const uint32_t smb = smem_u32(sm);
    const int crow = tid >> 3;              // 0..31 (+32*i)
    const int ckq = (tid & 7) << 2;         // 0,4,...,28

    // prologue: chunk 0 -> stage 0
    #pragma unroll
    for (int i = 0; i < 4; i++) {
        int row = crow + i * 32;
        CP_ASYNC16(smb + (uint32_t)(row * SMS + ckq) * 4,
                   A + (size_t)(m0 + row) * 512 + ckq);
        CP_ASYNC16(smb + (uint32_t)(128 * SMS + row * SMS + ckq) * 4,
                   B + (size_t)(n0row + row) * 512 + ckq);
    }
    CP_COMMIT();

    for (int kb = 0; kb < 16; kb++) {
        CP_WAIT0();
        __syncthreads();          // chunk kb visible; stage[(kb+1)&1] free

        const float* As = sm + (kb & 1) * GEMM_STAGE_FLT;
        const float* Bs = As + 128 * SMS;

        if (kb + 1 < 16) {
            uint32_t st = smb + (uint32_t)(((kb + 1) & 1) * GEMM_STAGE_FLT) * 4;
            int kc = (kb + 1) * 32;
            #pragma unroll
            for (int i = 0; i < 4; i++) {
                int row = crow + i * 32;
                CP_ASYNC16(st + (uint32_t)(row * SMS + ckq) * 4,
                           A + (size_t)(m0 + row) * 512 + kc + ckq);
                CP_ASYNC16(st + (uint32_t)(128 * SMS + row * SMS + ckq) * 4,
                           B + (size_t)(n0row + row) * 512 + kc + ckq);
            }
            CP_COMMIT();
        }

        #pragma unroll
        for (int ks = 0; ks < 4; ks++) {
            int k0 = ks * 8;
            uint32_t af[2][4];
            #pragma unroll
            for (int mt = 0; mt < 2; mt++) {
                int r0 = wm * 32 + mt * 16;
                af[mt][0] = f2tf32(As[(r0 + group) * SMS + k0 + qk]);
                af[mt][1] = f2tf32(As[(r0 + 8 + group) * SMS + k0 + qk]);
                af[mt][2] = f2tf32(As[(r0 + group) * SMS + k0 + 4 + qk]);
                af[mt][3] = f2tf32(As[(r0 + 8 + group) * SMS + k0 + 4 + qk]);
            }
            #pragma unroll
            for (int nt = 0; nt < 8; nt++) {
                int nr = wn * 64 + nt * 8;
                uint32_t bf[2];
                bf[0] = f2tf32(Bs[(nr + group) * SMS + k0 + qk]);
                bf[1] = f2tf32(Bs[(nr + group) * SMS + k0 + 4 + qk]);
                mma_tf32(c[0][nt], af[0], bf);
                mma_tf32(c[1][nt], af[1], bf);
            }
        }
    }
}

// ---------------------------------------------------------------------------
// Kernel 2: QKV projection (tf32 TC) with FUSED RoPE + q-scale epilogue.
// ---------------------------------------------------------------------------
__global__ void __launch_bounds__(256, 2)
qkv_gemm_tc_kernel(const float* __restrict__ wq,
                   const float* __restrict__ wk,
                   const float* __restrict__ wv) {
    extern __shared__ float dynsm[];

    int n0 = blockIdx.x * 128;
    int m0 = blockIdx.y * 128;
    int which = n0 >> 9;                 // 0=Q, 1=K, 2=V
    int cc0 = n0 & 511;
    const float* W = (which == 0) ? wq : ((which == 1) ? wk : wv);
    float* Dst = (which == 0) ? g_Q : ((which == 1) ? g_K : g_V);

    int tid = threadIdx.x;
    float c[2][8][4] = {};
    gemm_mainloop_tf32(g_XN, W, m0, cc0, dynsm, c, tid);

    const int lane = tid & 31;
    const int warp = tid >> 5;
    const int wm = warp & 3, wn = warp >> 2;
    const int group = lane >> 2, qk = lane & 3;

    #pragma unroll
    for (int mt = 0; mt < 2; mt++) {
        #pragma unroll
        for (int half = 0; half < 2; half++) {
            int m = m0 + wm * 32 + mt * 16 + group + half * 8;
            int r = m / T_SEQ;
            int t = m - r * T_SEQ;
            #pragma unroll
            for (int nt = 0; nt < 8; nt++) {
                int col = wn * 64 + nt * 8 + qk * 2;
                int cc = cc0 + col;
                int h = cc >> 6, dh = cc & 63;
                float2 v;
                v.x = c[mt][nt][half * 2 + 0];
                v.y = c[mt][nt][half * 2 + 1];
                if (which <= 1 && dh < 32) {
                    int i = dh >> 1;
                    float invf = __expf(-(float)i * 0.57564627324851142f);
                    float sn, cs;
                    sincosf((float)t * invf, &sn, &cs);
                    float a = v.x, b = v.y;
                    v.x = a * cs - b * sn;
                    v.y = a * sn + b * cs;
                }
                if (which == 0) { v.x *= 0.125f; v.y *= 0.125f; }
                *(float2*)(Dst + (((size_t)(r * H_HEADS + h) * T_SEQ) + t) * DHEAD + dh) = v;
            }
        }
    }
}

// ---------------------------------------------------------------------------
// Kernel 3: tensor-core causal flash attention (unchanged this round).
// ---------------------------------------------------------------------------
#define ATT_STR 68
#define ATT_SMEM_WORDS ((128 + 64 + 64 + 128) * ATT_STR)

__global__ void __launch_bounds__(256)
attn_tc_kernel(const int* __restrict__ pad_mask) {
    extern __shared__ uint32_t smu[];
    uint32_t* Qs = smu;
    uint32_t* Ks = Qs + 128 * ATT_STR;
    uint32_t* Vs = Ks + 64 * ATT_STR;
    uint32_t* Ps = Vs + 64 * ATT_STR;

    const int qt = blockIdx.x;
    const int rh = blockIdx.y;
    const int r = rh >> 3, h = rh & 7;
    const int qbase = qt * 128;

    const int tid = threadIdx.x;
    const int warp = tid >> 5;
    const int lane = tid & 31;
    const int g = lane >> 2;
    const int qk = lane & 3;
    const int wrow = warp * 16;

    const float* Qp = g_Q + ((size_t)rh * T_SEQ + qbase) * DHEAD;
    #pragma unroll
    for (int i = 0; i < 8; i++) {
        int idx = tid + i * 256;
        int row = idx >> 4, c4 = (idx & 15) << 2;
        float4 v = *(const float4*)(Qp + row * DHEAD + c4);
        uint32_t* qs = Qs + row * ATT_STR + c4;
        qs[0] = f2tf32(v.x); qs[1] = f2tf32(v.y);
        qs[2] = f2tf32(v.z); qs[3] = f2tf32(v.w);
    }

    float o[8][4] = {};
    float m0r = -1e30f, m1r = -1e30f;
    float l0r = 0.f, l1r = 0.f;

    const int ntiles = 2 * qt + 2;
    for (int kt = 0; kt < ntiles; kt++) {
        const int kbase = kt * 64;
        __syncthreads();
        const float* Kp = g_K + ((size_t)rh * T_SEQ + kbase) * DHEAD;
        const float* Vp = g_V + ((size_t)rh * T_SEQ + kbase) * DHEAD;
        #pragma unroll
        for (int i = 0; i < 4; i++) {
            int idx = tid + i * 256;
            int row = idx >> 4, c4 = (idx & 15) << 2;
            float4 kv = *(const float4*)(Kp + row * DHEAD + c4);
            uint32_t* ks = Ks + row * ATT_STR + c4;
            ks[0] = f2tf32(kv.x); ks[1] = f2tf32(kv.y);
            ks[2] = f2tf32(kv.z); ks[3] = f2tf32(kv.w);
            float4 vv = *(const float4*)(Vp + row * DHEAD + c4);
            uint32_t* vs = Vs + row * ATT_STR + c4;
            vs[0] = f2tf32(vv.x); vs[1] = f2tf32(vv.y);
            vs[2] = f2tf32(vv.z); vs[3] = f2tf32(vv.w);
        }
        __syncthreads();

        if (kbase > qbase + wrow + 15) continue;

        float s[8][4] = {};
        #pragma unroll
        for (int ks8 = 0; ks8 < 8; ks8++) {
            int k0 = ks8 * 8;
            uint32_t af[4];
            af[0] = Qs[(wrow + g) * ATT_STR + k0 + qk];
            af[1] = Qs[(wrow + 8 + g) * ATT_STR + k0 + qk];
            af[2] = Qs[(wrow + g) * ATT_STR + k0 + 4 + qk];
            af[3] = Qs[(wrow + 8 + g) * ATT_STR + k0 + 4 + qk];
            #pragma unroll
            for (int nt = 0; nt < 8; nt++) {
                uint32_t bf[2];
                bf[0] = Ks[(nt * 8 + g) * ATT_STR + k0 + qk];
                bf[1] = Ks[(nt * 8 + g) * ATT_STR + k0 + 4 + qk];
                mma_tf32(s[nt], af, bf);
            }
        }

        const int row0 = qbase + wrow + g;
        const int row1 = row0 + 8;

        if (kt >= 2 * qt) {
            #pragma unroll
            for (int nt = 0; nt < 8; nt++) {
                int c0 = kbase + nt * 8 + 2 * qk;
                if (c0 > row0)     s[nt][0] = -1e30f;
                if (c0 + 1 > row0) s[nt][1] = -1e30f;
                if (c0 > row1)     s[nt][2] = -1e30f;
                if (c0 + 1 > row1) s[nt][3] = -1e30f;
            }
        }

        float tmax0 = -1e30f, tmax1 = -1e30f;
        #pragma unroll
        for (int nt = 0; nt < 8; nt++) {
            tmax0 = fmaxf(tmax0, fmaxf(s[nt][0], s[nt][1]));
            tmax1 = fmaxf(tmax1, fmaxf(s[nt][2], s[nt][3]));
        }
        tmax0 = fmaxf(tmax0, __shfl_xor_sync(0xffffffffu, tmax0, 1));
        tmax0 = fmaxf(tmax0, __shfl_xor_sync(0xffffffffu, tmax0, 2));
        tmax1 = fmaxf(tmax1, __shfl_xor_sync(0xffffffffu, tmax1, 1));
        tmax1 = fmaxf(tmax1, __shfl_xor_sync(0xffffffffu, tmax1, 2));

        float nm0 = fmaxf(m0r, tmax0), nm1 = fmaxf(m1r, tmax1);
        float scl0 = __expf(m0r - nm0), scl1 = __expf(m1r - nm1);
        float ts0 = 0.f, ts1 = 0.f;
        #pragma unroll
        for (int nt = 0; nt < 8; nt++) {
            s[nt][0] = __expf(s[nt][0] - nm0);
            s[nt][1] = __expf(s[nt][1] - nm0);
            s[nt][2] = __expf(s[nt][2] - nm1);
            s[nt][3] = __expf(s[nt][3] - nm1);
            ts0 += s[nt][0] + s[nt][1];
            ts1 += s[nt][2] + s[nt][3];
        }
        ts0 += __shfl_xor_sync(0xffffffffu, ts0, 1);
        ts0 += __shfl_xor_sync(0xffffffffu, ts0, 2);
        ts1 += __shfl_xor_sync(0xffffffffu, ts1, 1);
        ts1 += __shfl_xor_sync(0xffffffffu, ts1, 2);
        l0r = l0r * scl0 + ts0;
        l1r = l1r * scl1 + ts1;
        m0r = nm0; m1r = nm1;
        #pragma unroll
        for (int nt = 0; nt < 8; nt++) {
            o[nt][0] *= scl0; o[nt][1] *= scl0;
            o[nt][2] *= scl1; o[nt][3] *= scl1;
        }

        #pragma unroll
        for (int nt = 0; nt < 8; nt++) {
            uint32_t* p0 = Ps + (wrow + g) * ATT_STR + nt * 8 + 2 * qk;
            *(uint2*)p0 = make_uint2(f2tf32(s[nt][0]), f2tf32(s[nt][1]));
            uint32_t* p1 = Ps + (wrow + 8 + g) * ATT_STR + nt * 8 + 2 * qk;
            *(uint2*)p1 = make_uint2(f2tf32(s[nt][2]), f2tf32(s[nt][3]));
        }
        __syncwarp();

        #pragma unroll
        for (int ks8 = 0; ks8 < 8; ks8++) {
            int k0 = ks8 * 8;
            uint32_t af[4];
            af[0] = Ps[(wrow + g) * ATT_STR + k0 + qk];
            af[1] = Ps[(wrow + 8 + g) * ATT_STR + k0 + qk];
            af[2] = Ps[(wrow + g) * ATT_STR + k0 + 4 + qk];
            af[3] = Ps[(wrow + 8 + g) * ATT_STR + k0 + 4 + qk];
            #pragma unroll
            for (int nt = 0; nt < 8; nt++) {
                uint32_t bf[2];
                bf[0] = Vs[(k0 + qk) * ATT_STR + nt * 8 + g];
                bf[1] = Vs[(k0 + 4 + qk) * ATT_STR + nt * 8 + g];
                mma_tf32(o[nt], af, bf);
            }
        }
    }

    const bool valid = (pad_mask[r] != 0);
    const float inv0 = 1.0f / l0r, inv1 = 1.0f / l1r;
    const int t0 = qbase + wrow + g;
    const int t1 = t0 + 8;
    #pragma unroll
    for (int nt = 0; nt < 8; nt++) {
        int dh = nt * 8 + 2 * qk;
        const float* xr0 = g_XN + ((size_t)r * T_SEQ + t0) * D_MOD + h * DHEAD + dh;
        float* yp0 = g_Y + ((size_t)t0 * N_NEU + r) * D_MOD + h * DHEAD + dh;
        float2 res0 = *(const float2*)xr0;
        float2 ov0;
        ov0.x = (valid ? o[nt][0] * inv0 : 0.f) + res0.x;
        ov0.y = (valid ? o[nt][1] * inv0 : 0.f) + res0.y;
        *(float2*)yp0 = ov0;

        const float* xr1 = g_XN + ((size_t)r * T_SEQ + t1) * D_MOD + h * DHEAD + dh;
        float* yp1 = g_Y + ((size_t)t1 * N_NEU + r) * D_MOD + h * DHEAD + dh;
        float2 res1 = *(const float2*)xr1;
        float2 ov1;
        ov1.x = (valid ? o[nt][2] * inv1 : 0.f) + res1.x;
        ov1.y = (valid ? o[nt][3] * inv1 : 0.f) + res1.y;
        *(float2*)yp1 = ov1;
    }
}

// ---------------------------------------------------------------------------
// Kernel 4: output projection (tf32 TC, cp.async pipeline).
// ---------------------------------------------------------------------------
__global__ void __launch_bounds__(256, 2)
out_gemm_tc_kernel(const float* __restrict__ wo,
                   float* __restrict__ out) {
    extern __shared__ float dynsm[];

    int n0 = blockIdx.x * 128;
    int m0 = blockIdx.y * 128;
    int tid = threadIdx.x;

    float c[2][8][4] = {};
    gemm_mainloop_tf32(g_Y, wo, m0, n0, dynsm, c, tid);

    const int lane = tid & 31;
    const int warp = tid >> 5;
    const int wm = warp & 3, wn = warp >> 2;
    const int group = lane >> 2, qk = lane & 3;

    #pragma unroll
    for (int mt = 0; mt < 2; mt++) {
        #pragma unroll
        for (int half = 0; half < 2; half++) {
            int m = m0 + wm * 32 + mt * 16 + group + half * 8;
            #pragma unroll
            for (int nt = 0; nt < 8; nt++) {
                int col = n0 + wn * 64 + nt * 8 + qk * 2;
                float2 v;
                v.x = c[mt][nt][half * 2 + 0];
                v.y = c[mt][nt][half * 2 + 1];
                *(float2*)(out + (size_t)m * 512 + col) = v;
            }
        }
    }
}

// ---------------------------------------------------------------------------
extern "C" void kernel_launch(void* const* d_in, const int* in_sizes, int n_in,
                              void* d_out, int out_size) {
    const float* x       = (const float*)d_in[0];
    const int*   pad     = (const int*)d_in[1];
    const float* norm_w  = (const float*)d_in[2];
    const float* wq      = (const float*)d_in[3];
    const float* wk      = (const float*)d_in[4];
    const float* wv      = (const float*)d_in[5];
    const float* wo      = (const float*)d_in[6];
    float* out = (float*)d_out;
    (void)in_sizes; (void)n_in; (void)out_size;

    cudaFuncSetAttribute(attn_tc_kernel,
                         cudaFuncAttributeMaxDynamicSharedMemorySize,
                         ATT_SMEM_WORDS * 4);
    cudaFuncSetAttribute(qkv_gemm_tc_kernel,
                         cudaFuncAttributeMaxDynamicSharedMemorySize,
                         GEMM_SMEM_BYTES);
    cudaFuncSetAttribute(out_gemm_tc_kernel,
                         cudaFuncAttributeMaxDynamicSharedMemorySize,
                         GEMM_SMEM_BYTES);

    // 1. RMSNorm + transpose
    rmsnorm_kernel<<<M_ROWS, 128>>>(x, norm_w);

    // 2. QKV projection (tf32 TC, cp.async) + fused RoPE/scale
    qkv_gemm_tc_kernel<<<dim3(1536 / 128, M_ROWS / 128), 256,
                         GEMM_SMEM_BYTES>>>(wq, wk, wv);

    // 3. tensor-core causal attention + mask + residual + transpose
    attn_tc_kernel<<<dim3(T_SEQ / 128, N_NEU * H_HEADS), 256,
                     ATT_SMEM_WORDS * 4>>>(pad);

    // 4. output projection (tf32 TC, cp.async)
    out_gemm_tc_kernel<<<dim3(512 / 128, M_ROWS / 128), 256,
                         GEMM_SMEM_BYTES>>>(wo, out);
}